// round 4
// baseline (speedup 1.0000x reference)
#include <cuda_runtime.h>
#include <cuda_bf16.h>
#include <cstdint>

// EdgeAtt fused: B=64, L=512, D=512. One 8-CTA cluster per batch,
// 64 rows per CTA. Phase1: dual projection (warp/row). e_j shared
// across cluster via DSMEM. Phase2: masked softmax, warp/row.

#define L_DIM 512
#define D_DIM 512
#define SLOPE 0.2f
#define CSIZE 8
#define ROWS_PER_CTA 64   // L_DIM / CSIZE

__global__ void __cluster_dims__(CSIZE, 1, 1) __launch_bounds__(256, 1)
k_fused(const float* __restrict__ nf, const float* __restrict__ wa,
        const float* __restrict__ ba, const int* __restrict__ tlen,
        float* __restrict__ out)
{
    __shared__ float sej[L_DIM];          // full e_j of this batch (filled via DSMEM)
    __shared__ float sei[ROWS_PER_CTA];   // e_i of this CTA's rows
    __shared__ float smax[8];

    const int tid  = threadIdx.x;
    const int warp = tid >> 5;
    const int lane = tid & 31;
    const int b    = blockIdx.x >> 3;     // batch
    const int c    = blockIdx.x & 7;      // rank within cluster
    const int row0 = c * ROWS_PER_CTA;

    const float4* w1 = reinterpret_cast<const float4*>(wa);
    const float4* w2 = reinterpret_cast<const float4*>(wa + D_DIM);

    // ---------------- phase 1: projections for 64 rows ----------------
    const size_t base = ((size_t)b * L_DIM + row0) * D_DIM;
    for (int lr = warp; lr < ROWS_PER_CTA; lr += 8) {
        const float4* row = reinterpret_cast<const float4*>(nf + base + (size_t)lr * D_DIM);
        float s1 = 0.f, s2 = 0.f;
#pragma unroll
        for (int t = 0; t < 4; t++) {
            int idx = lane + t * 32;
            float4 v = row[idx];
            float4 a = __ldg(&w1[idx]);
            float4 w = __ldg(&w2[idx]);
            s1 += v.x * a.x + v.y * a.y + v.z * a.z + v.w * a.w;
            s2 += v.x * w.x + v.y * w.y + v.z * w.z + v.w * w.w;
        }
#pragma unroll
        for (int o = 16; o; o >>= 1) {
            s1 += __shfl_xor_sync(0xffffffffu, s1, o);
            s2 += __shfl_xor_sync(0xffffffffu, s2, o);
        }
        if (lane == 0) sei[lr] = s1;
        // broadcast e_j to sej[row0+lr] of ALL cluster CTAs (8 lanes, 1 peer each)
        if (lane < CSIZE) {
            unsigned int laddr = (unsigned int)__cvta_generic_to_shared(&sej[row0 + lr]);
            unsigned int raddr;
            asm("mapa.shared::cluster.u32 %0, %1, %2;" : "=r"(raddr) : "r"(laddr), "r"(lane));
            asm volatile("st.shared::cluster.f32 [%0], %1;" :: "r"(raddr), "f"(s2) : "memory");
        }
    }

    // cluster barrier: all e_j writes visible everywhere after this
    asm volatile("barrier.cluster.arrive.aligned;" ::: "memory");
    asm volatile("barrier.cluster.wait.aligned;"   ::: "memory");

    // ---------------- phase 2: masked softmax ----------------
    const int len = tlen[b];

    // block max over valid e_j (leaky_relu monotonic -> analytic row max)
    const float v0 = sej[tid];
    const float v1 = sej[tid + 256];
    float mv = (tid < len) ? v0 : -1e30f;
    if (tid + 256 < len) mv = fmaxf(mv, v1);
#pragma unroll
    for (int o = 16; o; o >>= 1) mv = fmaxf(mv, __shfl_xor_sync(0xffffffffu, mv, o));
    if (lane == 0) smax[warp] = mv;
    __syncthreads();
    float mxej = smax[0];
#pragma unroll
    for (int k = 1; k < 8; k++) mxej = fmaxf(mxej, smax[k]);

    const float bias = __ldg(ba);

    for (int lr = warp; lr < ROWS_PER_CTA; lr += 8) {
        const int i = row0 + lr;
        float4* orow4 = reinterpret_cast<float4*>(out + ((size_t)b * L_DIM + i) * L_DIM);

        if (i >= len) {
            float4 z = make_float4(0.f, 0.f, 0.f, 0.f);
#pragma unroll
            for (int t = 0; t < 4; t++) orow4[t * 32 + lane] = z;
            continue;
        }

        const float ei   = sei[lr] + bias;
        const float mraw = ei + mxej;
        const float m    = mraw > 0.f ? mraw : SLOPE * mraw;  // exact row max

        float4 p[4];
        float s = 0.f;
#pragma unroll
        for (int t = 0; t < 4; t++) {
            const int j0 = t * 128 + lane * 4;
            float4 e4 = *reinterpret_cast<const float4*>(&sej[j0]);
            const int rem = len - j0;

            float v, pe;
            v = ei + e4.x; v = v > 0.f ? v : SLOPE * v;
            pe = (0 < rem) ? __expf(v - m) : 0.f; p[t].x = pe; s += pe;
            v = ei + e4.y; v = v > 0.f ? v : SLOPE * v;
            pe = (1 < rem) ? __expf(v - m) : 0.f; p[t].y = pe; s += pe;
            v = ei + e4.z; v = v > 0.f ? v : SLOPE * v;
            pe = (2 < rem) ? __expf(v - m) : 0.f; p[t].z = pe; s += pe;
            v = ei + e4.w; v = v > 0.f ? v : SLOPE * v;
            pe = (3 < rem) ? __expf(v - m) : 0.f; p[t].w = pe; s += pe;
        }
#pragma unroll
        for (int o = 16; o; o >>= 1) s += __shfl_xor_sync(0xffffffffu, s, o);

        const float inv = 1.f / s;
#pragma unroll
        for (int t = 0; t < 4; t++) {
            float4 r;
            r.x = p[t].x * inv; r.y = p[t].y * inv;
            r.z = p[t].z * inv; r.w = p[t].w * inv;
            orow4[t * 32 + lane] = r;
        }
    }
}

extern "C" void kernel_launch(void* const* d_in, const int* in_sizes, int n_in,
                              void* d_out, int out_size) {
    const float* nf   = (const float*)d_in[0];   // [B, L, D]
    const float* wa   = (const float*)d_in[1];   // [2D]
    const float* ba   = (const float*)d_in[2];   // [1]
    const int*   tlen = (const int*)d_in[3];     // [B]
    float* out = (float*)d_out;                  // [B, L, L]

    const int B = in_sizes[3];
    k_fused<<<B * CSIZE, 256>>>(nf, wa, ba, tlen, out);
}

// round 5
// speedup vs baseline: 1.3039x; 1.3039x over previous
#include <cuda_runtime.h>
#include <cuda_bf16.h>

// EdgeAtt: B=64, L=512, D=512  (two-kernel structure; R4 cluster fusion regressed)
//   e_i[b,l] = nf[b,l,:] . w_a[:D];  e_j[b,l] = nf[b,l,:] . w_a[D:]
//   A = softmax_j(lrelu(e_i+e_j+b) masked j>=len); rows i>=len zeroed.

#define L_DIM 512
#define D_DIM 512
#define SLOPE 0.2f
#define LOG2E 1.4426950408889634f
#define MASKV -1e9f

__device__ float g_ei[64 * L_DIM];
__device__ float g_ej[64 * L_DIM];

// ---------------- kernel 1: dual projection, warp per row ----------------
// Early-exits rows l >= text_len[b]: their projections are never consumed,
// which halves average DRAM read traffic.
__global__ void __launch_bounds__(256) k_proj(const float* __restrict__ nf,
                                              const float* __restrict__ wa,
                                              const int* __restrict__ tlen,
                                              int n_rows) {
    int r = (blockIdx.x * blockDim.x + threadIdx.x) >> 5;
    int lane = threadIdx.x & 31;
    if (r >= n_rows) return;
    const int b = r >> 9;          // L_DIM = 512
    const int l = r & (L_DIM - 1);
    if (l >= __ldg(&tlen[b])) return;   // unused projection -> skip the read

    const float4* row = reinterpret_cast<const float4*>(nf + (size_t)r * D_DIM);
    const float4* w1  = reinterpret_cast<const float4*>(wa);
    const float4* w2  = reinterpret_cast<const float4*>(wa + D_DIM);

    float s1 = 0.f, s2 = 0.f;
#pragma unroll
    for (int t = 0; t < 4; t++) {
        int idx = lane + t * 32;          // 128 float4 = 512 floats
        float4 v = row[idx];
        float4 a = __ldg(&w1[idx]);
        float4 w = __ldg(&w2[idx]);
        s1 += v.x * a.x + v.y * a.y + v.z * a.z + v.w * a.w;
        s2 += v.x * w.x + v.y * w.y + v.z * w.z + v.w * w.w;
    }
#pragma unroll
    for (int o = 16; o; o >>= 1) {
        s1 += __shfl_xor_sync(0xffffffffu, s1, o);
        s2 += __shfl_xor_sync(0xffffffffu, s2, o);
    }
    if (lane == 0) {
        g_ei[r] = s1;
        g_ej[r] = s2;
    }
}

// ---------------- kernel 2: masked softmax, warp per output row ----------------
// sej premasked to -1e9 for j>=len: exp underflows to exact 0, no per-element
// predicates in the hot loop. Row max analytic via monotonic leaky_relu.
__global__ void __launch_bounds__(256) k_soft(const float* __restrict__ ba,
                                              const int* __restrict__ tlen,
                                              float* __restrict__ out) {
    __shared__ float sej[L_DIM];
    __shared__ float smax[8];

    const int b    = blockIdx.y;
    const int tid  = threadIdx.x;
    const int warp = tid >> 5;
    const int lane = tid & 31;
    const int len  = tlen[b];

    // premasked load of e_j
    const float v0 = (tid       < len) ? g_ej[b * L_DIM + tid]       : MASKV;
    const float v1 = (tid + 256 < len) ? g_ej[b * L_DIM + tid + 256] : MASKV;
    sej[tid]       = v0;
    sej[tid + 256] = v1;

    // block max of premasked e_j (masked entries can't win; len >= 1)
    float mv = fmaxf(v0, v1);
#pragma unroll
    for (int o = 16; o; o >>= 1) mv = fmaxf(mv, __shfl_xor_sync(0xffffffffu, mv, o));
    if (lane == 0) smax[warp] = mv;
    __syncthreads();
    float mxej = smax[0];
#pragma unroll
    for (int k = 1; k < 8; k++) mxej = fmaxf(mxej, smax[k]);

    const int i = blockIdx.x * 8 + warp;
    float4* orow4 = reinterpret_cast<float4*>(out + ((size_t)b * L_DIM + i) * L_DIM);

    if (i >= len) {
        float4 z = make_float4(0.f, 0.f, 0.f, 0.f);
#pragma unroll
        for (int t = 0; t < 4; t++) orow4[t * 32 + lane] = z;
        return;
    }

    const float ei   = g_ei[b * L_DIM + i] + __ldg(ba);
    const float mraw = ei + mxej;
    const float m    = fmaxf(mraw, SLOPE * mraw);   // exact row max
    const float mc   = m * LOG2E;

    float4 p[4];
    float s = 0.f;
#pragma unroll
    for (int t = 0; t < 4; t++) {
        const int j0 = t * 128 + lane * 4;
        float4 e4 = *reinterpret_cast<const float4*>(&sej[j0]);

        float v, lr, pe;
        v = ei + e4.x; lr = fmaxf(v, SLOPE * v);
        pe = exp2f(fmaf(lr, LOG2E, -mc)); p[t].x = pe; s += pe;
        v = ei + e4.y; lr = fmaxf(v, SLOPE * v);
        pe = exp2f(fmaf(lr, LOG2E, -mc)); p[t].y = pe; s += pe;
        v = ei + e4.z; lr = fmaxf(v, SLOPE * v);
        pe = exp2f(fmaf(lr, LOG2E, -mc)); p[t].z = pe; s += pe;
        v = ei + e4.w; lr = fmaxf(v, SLOPE * v);
        pe = exp2f(fmaf(lr, LOG2E, -mc)); p[t].w = pe; s += pe;
    }
#pragma unroll
    for (int o = 16; o; o >>= 1) s += __shfl_xor_sync(0xffffffffu, s, o);

    const float inv = 1.f / s;
#pragma unroll
    for (int t = 0; t < 4; t++) {
        float4 r;
        r.x = p[t].x * inv; r.y = p[t].y * inv;
        r.z = p[t].z * inv; r.w = p[t].w * inv;
        orow4[t * 32 + lane] = r;
    }
}

extern "C" void kernel_launch(void* const* d_in, const int* in_sizes, int n_in,
                              void* d_out, int out_size) {
    const float* nf   = (const float*)d_in[0];   // [B, L, D]
    const float* wa   = (const float*)d_in[1];   // [2D]
    const float* ba   = (const float*)d_in[2];   // [1]
    const int*   tlen = (const int*)d_in[3];     // [B]
    float* out = (float*)d_out;                  // [B, L, L]

    const int B = in_sizes[3];
    const int n_rows = B * L_DIM;

    k_proj<<<(n_rows + 7) / 8, 256>>>(nf, wa, tlen, n_rows);

    dim3 grid(L_DIM / 8, B);
    k_soft<<<grid, 256>>>(ba, tlen, out);
}

// round 6
// speedup vs baseline: 1.7432x; 1.3370x over previous
#include <cuda_runtime.h>
#include <cuda_bf16.h>

// EdgeAtt: B=64, L=512, D=512
// k_soft uses exp-factorization over the leaky_relu pieces:
//   v>0:  exp(v-m)     = E1 * f1[j],  f1[j]=exp(ej-mxej)
//   v<=0: exp(0.2v-m)  = E2 * f2[j],  f2[j]=exp(0.2(ej-mxej))
// sign(v) via threshold: v>0  <=>  f1[j] > exp(-ei-mxej)

#define L_DIM 512
#define D_DIM 512
#define SLOPE 0.2f
#define MASKV -1e9f

__device__ float g_ei[64 * L_DIM];
__device__ float g_ej[64 * L_DIM];

// ---------------- kernel 1: dual projection, warp per row ----------------
__global__ void __launch_bounds__(256) k_proj(const float* __restrict__ nf,
                                              const float* __restrict__ wa,
                                              const int* __restrict__ tlen,
                                              int n_rows) {
    int r = (blockIdx.x * blockDim.x + threadIdx.x) >> 5;
    int lane = threadIdx.x & 31;
    if (r >= n_rows) return;
    const int b = r >> 9;
    const int l = r & (L_DIM - 1);
    if (l >= __ldg(&tlen[b])) return;   // projection never consumed

    const float4* row = reinterpret_cast<const float4*>(nf + (size_t)r * D_DIM);
    const float4* w1  = reinterpret_cast<const float4*>(wa);
    const float4* w2  = reinterpret_cast<const float4*>(wa + D_DIM);

    float s1 = 0.f, s2 = 0.f;
#pragma unroll
    for (int t = 0; t < 4; t++) {
        int idx = lane + t * 32;
        float4 v = row[idx];
        float4 a = __ldg(&w1[idx]);
        float4 w = __ldg(&w2[idx]);
        s1 += v.x * a.x + v.y * a.y + v.z * a.z + v.w * a.w;
        s2 += v.x * w.x + v.y * w.y + v.z * w.z + v.w * w.w;
    }
#pragma unroll
    for (int o = 16; o; o >>= 1) {
        s1 += __shfl_xor_sync(0xffffffffu, s1, o);
        s2 += __shfl_xor_sync(0xffffffffu, s2, o);
    }
    if (lane == 0) {
        g_ei[r] = s1;
        g_ej[r] = s2;
    }
}

// ---------------- kernel 2: masked softmax, warp per output row ----------------
__global__ void __launch_bounds__(256) k_soft(const float* __restrict__ ba,
                                              const int* __restrict__ tlen,
                                              float* __restrict__ out) {
    __shared__ float sf1[L_DIM];
    __shared__ float sf2[L_DIM];
    __shared__ float smax[8];

    const int b    = blockIdx.y;
    const int tid  = threadIdx.x;
    const int warp = tid >> 5;
    const int lane = tid & 31;
    const int len  = tlen[b];

    // premasked e_j
    const float v0 = (tid       < len) ? g_ej[b * L_DIM + tid]       : MASKV;
    const float v1 = (tid + 256 < len) ? g_ej[b * L_DIM + tid + 256] : MASKV;

    // block max of premasked e_j (len >= 1 so a real value wins)
    float mv = fmaxf(v0, v1);
#pragma unroll
    for (int o = 16; o; o >>= 1) mv = fmaxf(mv, __shfl_xor_sync(0xffffffffu, mv, o));
    if (lane == 0) smax[warp] = mv;
    __syncthreads();
    float mxej = smax[0];
#pragma unroll
    for (int k = 1; k < 8; k++) mxej = fmaxf(mxej, smax[k]);

    // factorization tables (exponents <= 0 -> in (0,1]; masked j -> exactly 0)
    sf1[tid]       = __expf(v0 - mxej);
    sf1[tid + 256] = __expf(v1 - mxej);
    sf2[tid]       = __expf(SLOPE * (v0 - mxej));
    sf2[tid + 256] = __expf(SLOPE * (v1 - mxej));
    __syncthreads();

    const int i = blockIdx.x * 8 + warp;
    float4* orow4 = reinterpret_cast<float4*>(out + ((size_t)b * L_DIM + i) * L_DIM);

    if (i >= len) {
        float4 z = make_float4(0.f, 0.f, 0.f, 0.f);
#pragma unroll
        for (int t = 0; t < 4; t++) orow4[t * 32 + lane] = z;
        return;
    }

    const float ei   = g_ei[b * L_DIM + i] + __ldg(ba);
    const float mraw = ei + mxej;
    const float m    = fmaxf(mraw, SLOPE * mraw);          // exact row max
    const float E1   = __expf(mraw - m);                   // positive-branch row factor
    const float E2   = __expf(SLOPE * mraw - m);           // negative-branch row factor
    const float T    = __expf(-ei - mxej);                 // f1[j] > T  <=>  ei+ej > 0

    float4 p[4];
    float s = 0.f;
#pragma unroll
    for (int t = 0; t < 4; t++) {
        const int j0 = t * 128 + lane * 4;
        float4 f1 = *reinterpret_cast<const float4*>(&sf1[j0]);
        float4 f2 = *reinterpret_cast<const float4*>(&sf2[j0]);

        float pe;
        pe = (f1.x > T) ? f1.x * E1 : f2.x * E2; p[t].x = pe; s += pe;
        pe = (f1.y > T) ? f1.y * E1 : f2.y * E2; p[t].y = pe; s += pe;
        pe = (f1.z > T) ? f1.z * E1 : f2.z * E2; p[t].z = pe; s += pe;
        pe = (f1.w > T) ? f1.w * E1 : f2.w * E2; p[t].w = pe; s += pe;
    }
#pragma unroll
    for (int o = 16; o; o >>= 1) s += __shfl_xor_sync(0xffffffffu, s, o);

    const float inv = 1.f / s;
#pragma unroll
    for (int t = 0; t < 4; t++) {
        float4 r;
        r.x = p[t].x * inv; r.y = p[t].y * inv;
        r.z = p[t].z * inv; r.w = p[t].w * inv;
        orow4[t * 32 + lane] = r;
    }
}

extern "C" void kernel_launch(void* const* d_in, const int* in_sizes, int n_in,
                              void* d_out, int out_size) {
    const float* nf   = (const float*)d_in[0];   // [B, L, D]
    const float* wa   = (const float*)d_in[1];   // [2D]
    const float* ba   = (const float*)d_in[2];   // [1]
    const int*   tlen = (const int*)d_in[3];     // [B]
    float* out = (float*)d_out;                  // [B, L, L]

    const int B = in_sizes[3];
    const int n_rows = B * L_DIM;

    k_proj<<<(n_rows + 7) / 8, 256>>>(nf, wa, tlen, n_rows);

    dim3 grid(L_DIM / 8, B);
    k_soft<<<grid, 256>>>(ba, tlen, out);
}

// round 7
// speedup vs baseline: 1.7819x; 1.0222x over previous
#include <cuda_runtime.h>
#include <cuda_bf16.h>

// EdgeAtt: B=64, L=512, D=512
// k_soft: exp-factorization over leaky_relu pieces + 64 rows/block,
// tables cached in registers across the row loop.

#define L_DIM 512
#define D_DIM 512
#define SLOPE 0.2f
#define MASKV -1e9f

__device__ float g_ei[64 * L_DIM];
__device__ float g_ej[64 * L_DIM];

// ---------------- kernel 1: dual projection, warp per row ----------------
__global__ void __launch_bounds__(256) k_proj(const float* __restrict__ nf,
                                              const float* __restrict__ wa,
                                              const int* __restrict__ tlen,
                                              int n_rows) {
    int r = (blockIdx.x * blockDim.x + threadIdx.x) >> 5;
    int lane = threadIdx.x & 31;
    if (r >= n_rows) return;
    const int b = r >> 9;
    const int l = r & (L_DIM - 1);
    if (l >= __ldg(&tlen[b])) return;   // projection never consumed

    const float4* row = reinterpret_cast<const float4*>(nf + (size_t)r * D_DIM);
    const float4* w1  = reinterpret_cast<const float4*>(wa);
    const float4* w2  = reinterpret_cast<const float4*>(wa + D_DIM);

    float s1 = 0.f, s2 = 0.f;
#pragma unroll
    for (int t = 0; t < 4; t++) {
        int idx = lane + t * 32;
        float4 v = row[idx];
        float4 a = __ldg(&w1[idx]);
        float4 w = __ldg(&w2[idx]);
        s1 += v.x * a.x + v.y * a.y + v.z * a.z + v.w * a.w;
        s2 += v.x * w.x + v.y * w.y + v.z * w.z + v.w * w.w;
    }
#pragma unroll
    for (int o = 16; o; o >>= 1) {
        s1 += __shfl_xor_sync(0xffffffffu, s1, o);
        s2 += __shfl_xor_sync(0xffffffffu, s2, o);
    }
    if (lane == 0) {
        g_ei[r] = s1;
        g_ej[r] = s2;
    }
}

// ---------------- kernel 2: masked softmax, 64 rows per block ----------------
__global__ void __launch_bounds__(256) k_soft(const float* __restrict__ ba,
                                              const int* __restrict__ tlen,
                                              float* __restrict__ out) {
    __shared__ float sf1[L_DIM];
    __shared__ float sf2[L_DIM];
    __shared__ float smax[8];

    const int b    = blockIdx.x >> 3;
    const int c    = blockIdx.x & 7;
    const int row0 = c * 64;
    const int tid  = threadIdx.x;
    const int warp = tid >> 5;
    const int lane = tid & 31;
    const int len  = tlen[b];

    // premasked e_j
    const float v0 = (tid       < len) ? g_ej[b * L_DIM + tid]       : MASKV;
    const float v1 = (tid + 256 < len) ? g_ej[b * L_DIM + tid + 256] : MASKV;

    // block max of premasked e_j (len >= 1)
    float mv = fmaxf(v0, v1);
#pragma unroll
    for (int o = 16; o; o >>= 1) mv = fmaxf(mv, __shfl_xor_sync(0xffffffffu, mv, o));
    if (lane == 0) smax[warp] = mv;
    __syncthreads();
    float mxej = smax[0];
#pragma unroll
    for (int k = 1; k < 8; k++) mxej = fmaxf(mxej, smax[k]);

    // factorization tables (exponents <= 0; masked j -> exactly 0)
    sf1[tid]       = __expf(v0 - mxej);
    sf1[tid + 256] = __expf(v1 - mxej);
    sf2[tid]       = __expf(SLOPE * (v0 - mxej));
    sf2[tid + 256] = __expf(SLOPE * (v1 - mxej));
    __syncthreads();

    // cache this lane's table slices in registers (column layout j0 = t*128 + lane*4)
    float4 f1c[4], f2c[4];
#pragma unroll
    for (int t = 0; t < 4; t++) {
        const int j0 = t * 128 + lane * 4;
        f1c[t] = *reinterpret_cast<const float4*>(&sf1[j0]);
        f2c[t] = *reinterpret_cast<const float4*>(&sf2[j0]);
    }

    const float bias = __ldg(ba);
    const float* gei = g_ei + b * L_DIM;
    float* obase = out + ((size_t)b * L_DIM + row0) * L_DIM;

    // each warp: 8 contiguous rows [row0 + warp*8, +8)
#pragma unroll
    for (int t8 = 0; t8 < 8; t8++) {
        const int lr = warp * 8 + t8;         // local row
        const int i  = row0 + lr;
        float4* orow4 = reinterpret_cast<float4*>(obase + (size_t)lr * L_DIM);

        if (i >= len) {
            float4 z = make_float4(0.f, 0.f, 0.f, 0.f);
#pragma unroll
            for (int t = 0; t < 4; t++) orow4[t * 32 + lane] = z;
            continue;
        }

        const float ei   = gei[i] + bias;
        const float mraw = ei + mxej;
        const float m    = fmaxf(mraw, SLOPE * mraw);      // exact row max
        const float E1   = __expf(mraw - m);
        const float E2   = __expf(SLOPE * mraw - m);
        const float T    = __expf(-ei - mxej);             // f1 > T <=> ei+ej > 0

        float4 p[4];
        float s = 0.f;
#pragma unroll
        for (int t = 0; t < 4; t++) {
            float pe;
            pe = (f1c[t].x > T) ? f1c[t].x * E1 : f2c[t].x * E2; p[t].x = pe; s += pe;
            pe = (f1c[t].y > T) ? f1c[t].y * E1 : f2c[t].y * E2; p[t].y = pe; s += pe;
            pe = (f1c[t].z > T) ? f1c[t].z * E1 : f2c[t].z * E2; p[t].z = pe; s += pe;
            pe = (f1c[t].w > T) ? f1c[t].w * E1 : f2c[t].w * E2; p[t].w = pe; s += pe;
        }
#pragma unroll
        for (int o = 16; o; o >>= 1) s += __shfl_xor_sync(0xffffffffu, s, o);

        const float inv = 1.f / s;
#pragma unroll
        for (int t = 0; t < 4; t++) {
            float4 r;
            r.x = p[t].x * inv; r.y = p[t].y * inv;
            r.z = p[t].z * inv; r.w = p[t].w * inv;
            orow4[t * 32 + lane] = r;
        }
    }
}

extern "C" void kernel_launch(void* const* d_in, const int* in_sizes, int n_in,
                              void* d_out, int out_size) {
    const float* nf   = (const float*)d_in[0];   // [B, L, D]
    const float* wa   = (const float*)d_in[1];   // [2D]
    const float* ba   = (const float*)d_in[2];   // [1]
    const int*   tlen = (const int*)d_in[3];     // [B]
    float* out = (float*)d_out;                  // [B, L, L]

    const int B = in_sizes[3];
    const int n_rows = B * L_DIM;

    k_proj<<<(n_rows + 7) / 8, 256>>>(nf, wa, tlen, n_rows);

    k_soft<<<B * 8, 256>>>(ba, tlen, out);
}